// round 9
// baseline (speedup 1.0000x reference)
#include <cuda_runtime.h>
#include <cstdint>

// ---------------------------------------------------------------------------
// 64 attention instances: instance i uses contiguous slab [i*65536,(i+1)*65536)
// of each projection viewed as (1024,64).
// Accuracy: Q/K-proj + QK^T via 4xTF32 split MMA (hh+hl+lh+ll: product exact,
// only fp32-accum reorder noise -> no mask flips). V-proj/out: 3xTF32.
// PV: 2xTF32 (A hi only) -> ~3e-4 smooth error, deterministic inputs.
// Stats partials fused into qk epilogue; pv accumulates softmax Z inline.
// ---------------------------------------------------------------------------
#define NORMF 0.04419417382415922f   // 1/sqrt(512)

static __device__ float g_Qp[8192 * 512];
static __device__ float g_Kp[8192 * 512];
static __device__ float g_Vp[8192 * 512];
static __device__ float g_AO[8192 * 512];
static __device__ float g_S[67108864];        // 64*1024*1024 scores
static __device__ float2 g_part[65536 * 32];  // per (row, 32-col block): sum, max
static __device__ float2 g_stats2[65536];     // per row: mean, max

__device__ __forceinline__ float tf32r(float x) {
    uint32_t u;
    asm("cvt.rna.tf32.f32 %0, %1;" : "=r"(u) : "f"(x));
    return __uint_as_float(u);
}

#define MMA8(d, a, b)                                                          \
    asm volatile("mma.sync.aligned.m16n8k8.row.col.f32.tf32.tf32.f32 "         \
                 "{%0,%1,%2,%3}, {%4,%5,%6,%7}, {%8,%9}, {%0,%1,%2,%3};"       \
                 : "+f"((d)[0]), "+f"((d)[1]), "+f"((d)[2]), "+f"((d)[3])      \
                 : "r"((a)[0]), "r"((a)[1]), "r"((a)[2]), "r"((a)[3]),         \
                   "r"((b)[0]), "r"((b)[1]))

// ===========================================================================
// mm_core<NTERMS>: split-tf32 GEMM body. Block tile 128x64x16, 256 thr,
// 8 warps (4m x 2n). B is K x N (B[k][n]). NTERMS=3: hh+hl+lh.
// NTERMS=4: + ll (product-exact -> fp32-grade result).
// Smem fragment order: A planes [16 tiles][32 lanes][4], B planes [16][32][2].
// Stage = 24KB; 2 stages = 48KB.
// ===========================================================================
template <int NTERMS>
__device__ __forceinline__ void mm_core(
    const float* __restrict__ A, int lda,
    const float* __restrict__ B, int ldb,
    const float* __restrict__ bias,
    float* __restrict__ C, int ldc, int ktot)
{
    extern __shared__ float sm[];
    const int tid = threadIdx.x;
    const int lane = tid & 31, wid = tid >> 5;
    const int wm = wid & 3, wn = wid >> 2;

    int tA[2], rA[2], cA[2];
#pragma unroll
    for (int sl = 0; sl < 2; sl++) {
        int slot = tid + sl * 256;
        tA[sl] = slot >> 5; rA[sl] = (slot & 31) >> 2; cA[sl] = slot & 3;
    }

    float acc[2][4][4];
#pragma unroll
    for (int mt = 0; mt < 2; mt++)
#pragma unroll
        for (int nt = 0; nt < 4; nt++)
#pragma unroll
            for (int e = 0; e < 4; e++) acc[mt][nt][e] = 0.f;

    float ax[2][4], bx[2][2];

    auto LDF = [&](int kb) {
#pragma unroll
        for (int sl = 0; sl < 2; sl++) {
            int tm = tA[sl] & 7, tk = tA[sl] >> 3;
            const float* p = A + (size_t)(tm * 16 + rA[sl]) * lda + kb + tk * 8 + cA[sl];
            const float* q = p + 8 * (size_t)lda;
            ax[sl][0] = p[0]; ax[sl][1] = q[0];
            ax[sl][2] = p[4]; ax[sl][3] = q[4];
        }
#pragma unroll
        for (int sl = 0; sl < 2; sl++) {
            int tn = tA[sl] & 7, tk = tA[sl] >> 3;
            int n = tn * 8 + rA[sl];
            int kc = kb + tk * 8 + cA[sl];
            const float* p = B + (size_t)kc * ldb + n;
            bx[sl][0] = p[0]; bx[sl][1] = p[4 * (size_t)ldb];
        }
    };

    auto STF = [&](int s) {
        float* base = sm + s * 6144;
#pragma unroll
        for (int sl = 0; sl < 2; sl++) {
            float4 h, l;
            h.x = tf32r(ax[sl][0]); l.x = tf32r(ax[sl][0] - h.x);
            h.y = tf32r(ax[sl][1]); l.y = tf32r(ax[sl][1] - h.y);
            h.z = tf32r(ax[sl][2]); l.z = tf32r(ax[sl][2] - h.z);
            h.w = tf32r(ax[sl][3]); l.w = tf32r(ax[sl][3] - h.w);
            int slot = tid + sl * 256;
            int off = (slot >> 5) * 128 + (slot & 31) * 4;
            *(float4*)(base + off) = h;
            *(float4*)(base + 2048 + off) = l;
        }
#pragma unroll
        for (int sl = 0; sl < 2; sl++) {
            float2 h, l;
            h.x = tf32r(bx[sl][0]); l.x = tf32r(bx[sl][0] - h.x);
            h.y = tf32r(bx[sl][1]); l.y = tf32r(bx[sl][1] - h.y);
            int slot = tid + sl * 256;
            int off = (slot >> 5) * 64 + (slot & 31) * 2;
            *(float2*)(base + 4096 + off) = h;
            *(float2*)(base + 5120 + off) = l;
        }
    };

    auto CMP = [&](int s) {
        const float* base = sm + s * 6144;
#pragma unroll
        for (int tk = 0; tk < 2; tk++) {
            uint4 ah[2], al[2];
            uint2 bh[4], bl[4];
#pragma unroll
            for (int mt = 0; mt < 2; mt++) {
                int tg = tk * 8 + wm * 2 + mt;
                ah[mt] = *(const uint4*)(base + tg * 128 + lane * 4);
                al[mt] = *(const uint4*)(base + 2048 + tg * 128 + lane * 4);
            }
#pragma unroll
            for (int nt = 0; nt < 4; nt++) {
                int tg = tk * 8 + wn * 4 + nt;
                bh[nt] = *(const uint2*)(base + 4096 + tg * 64 + lane * 2);
                bl[nt] = *(const uint2*)(base + 5120 + tg * 64 + lane * 2);
            }
#pragma unroll
            for (int mt = 0; mt < 2; mt++)
#pragma unroll
                for (int nt = 0; nt < 4; nt++) {
                    MMA8(acc[mt][nt], (&ah[mt].x), (&bh[nt].x));
                    MMA8(acc[mt][nt], (&ah[mt].x), (&bl[nt].x));
                    MMA8(acc[mt][nt], (&al[mt].x), (&bh[nt].x));
                    if (NTERMS == 4)
                        MMA8(acc[mt][nt], (&al[mt].x), (&bl[nt].x));
                }
        }
    };

    const int nk = ktot / 16;
    LDF(0);
    STF(0);
    __syncthreads();
    for (int i = 0; i < nk; i++) {
        if (i + 1 < nk) LDF((i + 1) * 16);
        CMP(i & 1);
        if (i + 1 < nk) STF((i + 1) & 1);
        __syncthreads();
    }

#pragma unroll
    for (int mt = 0; mt < 2; mt++)
#pragma unroll
        for (int nt = 0; nt < 4; nt++) {
            int row = wm * 32 + mt * 16 + (lane >> 2);
            int col = wn * 32 + nt * 8 + (lane & 3) * 2;
            float b0 = bias[col], b1 = bias[col + 1];
            *(float2*)(C + (size_t)row * ldc + col) =
                make_float2(acc[mt][nt][0] + b0, acc[mt][nt][1] + b1);
            *(float2*)(C + (size_t)(row + 8) * ldc + col) =
                make_float2(acc[mt][nt][2] + b0, acc[mt][nt][3] + b1);
        }
}

// ---------------------------------------------------------------------------
// proj_all: all three projections in ONE launch.
// z=0: Q = x@qw+qb (4-term), z=1: K = y@kw+kb (4-term), z=2: V = y@vw+vb (3-term)
// ---------------------------------------------------------------------------
__global__ void __launch_bounds__(256, 2) proj_all(
    const float* __restrict__ x, const float* __restrict__ y,
    const float* __restrict__ qw, const float* __restrict__ qb,
    const float* __restrict__ kw, const float* __restrict__ kb,
    const float* __restrict__ vw, const float* __restrict__ vb)
{
    int row0 = blockIdx.y * 128, col0 = blockIdx.x * 64;
    if (blockIdx.z == 0) {
        mm_core<4>(x + (size_t)row0 * 512, 512, qw + col0, 512,
                   qb + col0, g_Qp + (size_t)row0 * 512 + col0, 512, 512);
    } else if (blockIdx.z == 1) {
        mm_core<4>(y + (size_t)row0 * 512, 512, kw + col0, 512,
                   kb + col0, g_Kp + (size_t)row0 * 512 + col0, 512, 512);
    } else {
        mm_core<3>(y + (size_t)row0 * 512, 512, vw + col0, 512,
                   vb + col0, g_Vp + (size_t)row0 * 512 + col0, 512, 512);
    }
}

__global__ void __launch_bounds__(256, 2) out_mm(
    const float* __restrict__ ow, const float* __restrict__ ob,
    float* __restrict__ out)
{
    int row0 = blockIdx.y * 128, col0 = blockIdx.x * 64;
    mm_core<3>(g_AO + (size_t)row0 * 512, 512, ow + col0, 512,
               ob + col0, out + (size_t)row0 * 512 + col0, 512, 512);
}

// ===========================================================================
// qk_tf32: S = (Q @ K^T) * NORM. 4-term split on fp32-grade Q/K.
// Fused per-(row, 32-col) stat partials. B operand is K-major (K rows x 64).
// ===========================================================================
__global__ void __launch_bounds__(256, 2) qk_tf32()
{
    extern __shared__ float sm[];
    const int tid = threadIdx.x;
    const int lane = tid & 31, wid = tid >> 5;
    const int wm = wid & 3, wn = wid >> 2;
    const int inst = blockIdx.z;
    const int row0 = blockIdx.y * 128, col0 = blockIdx.x * 64;
    const float* A = g_Qp + (size_t)inst * 65536 + (size_t)row0 * 64;
    const float* B = g_Kp + (size_t)inst * 65536 + (size_t)col0 * 64;
    float* Sout = g_S + ((size_t)inst << 20) + (size_t)row0 * 1024 + col0;

    int tA[2], rA[2], cA[2];
#pragma unroll
    for (int sl = 0; sl < 2; sl++) {
        int slot = tid + sl * 256;
        tA[sl] = slot >> 5; rA[sl] = (slot & 31) >> 2; cA[sl] = slot & 3;
    }

    float acc[2][4][4];
#pragma unroll
    for (int mt = 0; mt < 2; mt++)
#pragma unroll
        for (int nt = 0; nt < 4; nt++)
#pragma unroll
            for (int e = 0; e < 4; e++) acc[mt][nt][e] = 0.f;

    float ax[2][4], bx[2][2];

    auto LDF = [&](int kb) {
#pragma unroll
        for (int sl = 0; sl < 2; sl++) {
            int tm = tA[sl] & 7, tk = tA[sl] >> 3;
            const float* p = A + (size_t)(tm * 16 + rA[sl]) * 64 + kb + tk * 8 + cA[sl];
            const float* q = p + 8 * 64;
            ax[sl][0] = p[0]; ax[sl][1] = q[0];
            ax[sl][2] = p[4]; ax[sl][3] = q[4];
        }
#pragma unroll
        for (int sl = 0; sl < 2; sl++) {
            int tn = tA[sl] & 7, tk = tA[sl] >> 3;
            const float* p = B + (size_t)(tn * 8 + rA[sl]) * 64 + kb + tk * 8 + cA[sl];
            bx[sl][0] = p[0]; bx[sl][1] = p[4];
        }
    };

    auto STF = [&](int s) {
        float* base = sm + s * 6144;
#pragma unroll
        for (int sl = 0; sl < 2; sl++) {
            float4 h, l;
            h.x = tf32r(ax[sl][0]); l.x = tf32r(ax[sl][0] - h.x);
            h.y = tf32r(ax[sl][1]); l.y = tf32r(ax[sl][1] - h.y);
            h.z = tf32r(ax[sl][2]); l.z = tf32r(ax[sl][2] - h.z);
            h.w = tf32r(ax[sl][3]); l.w = tf32r(ax[sl][3] - h.w);
            int slot = tid + sl * 256;
            int off = (slot >> 5) * 128 + (slot & 31) * 4;
            *(float4*)(base + off) = h;
            *(float4*)(base + 2048 + off) = l;
        }
#pragma unroll
        for (int sl = 0; sl < 2; sl++) {
            float2 h, l;
            h.x = tf32r(bx[sl][0]); l.x = tf32r(bx[sl][0] - h.x);
            h.y = tf32r(bx[sl][1]); l.y = tf32r(bx[sl][1] - h.y);
            int slot = tid + sl * 256;
            int off = (slot >> 5) * 64 + (slot & 31) * 2;
            *(float2*)(base + 4096 + off) = h;
            *(float2*)(base + 5120 + off) = l;
        }
    };

    auto CMP = [&](int s) {
        const float* base = sm + s * 6144;
#pragma unroll
        for (int tk = 0; tk < 2; tk++) {
            uint4 ah[2], al[2];
            uint2 bh[4], bl[4];
#pragma unroll
            for (int mt = 0; mt < 2; mt++) {
                int tg = tk * 8 + wm * 2 + mt;
                ah[mt] = *(const uint4*)(base + tg * 128 + lane * 4);
                al[mt] = *(const uint4*)(base + 2048 + tg * 128 + lane * 4);
            }
#pragma unroll
            for (int nt = 0; nt < 4; nt++) {
                int tg = tk * 8 + wn * 4 + nt;
                bh[nt] = *(const uint2*)(base + 4096 + tg * 64 + lane * 2);
                bl[nt] = *(const uint2*)(base + 5120 + tg * 64 + lane * 2);
            }
#pragma unroll
            for (int mt = 0; mt < 2; mt++)
#pragma unroll
                for (int nt = 0; nt < 4; nt++) {
                    MMA8(acc[mt][nt], (&ah[mt].x), (&bh[nt].x));
                    MMA8(acc[mt][nt], (&ah[mt].x), (&bl[nt].x));
                    MMA8(acc[mt][nt], (&al[mt].x), (&bh[nt].x));
                    MMA8(acc[mt][nt], (&al[mt].x), (&bl[nt].x));
                }
        }
    };

    LDF(0);
    STF(0);
    __syncthreads();
    for (int i = 0; i < 4; i++) {
        if (i + 1 < 4) LDF((i + 1) * 16);
        CMP(i & 1);
        if (i + 1 < 4) STF((i + 1) & 1);
        __syncthreads();
    }

#pragma unroll
    for (int mt = 0; mt < 2; mt++) {
#pragma unroll
        for (int half = 0; half < 2; half++) {
            int row = wm * 32 + mt * 16 + (lane >> 2) + half * 8;
            float v[8];
#pragma unroll
            for (int nt = 0; nt < 4; nt++) {
                v[nt * 2 + 0] = acc[mt][nt][half * 2 + 0] * NORMF;
                v[nt * 2 + 1] = acc[mt][nt][half * 2 + 1] * NORMF;
                int col = wn * 32 + nt * 8 + (lane & 3) * 2;
                *(float2*)(Sout + (size_t)row * 1024 + col) =
                    make_float2(v[nt * 2], v[nt * 2 + 1]);
            }
            float s8 = ((v[0] + v[1]) + (v[2] + v[3])) + ((v[4] + v[5]) + (v[6] + v[7]));
            float m8 = fmaxf(fmaxf(fmaxf(v[0], v[1]), fmaxf(v[2], v[3])),
                             fmaxf(fmaxf(v[4], v[5]), fmaxf(v[6], v[7])));
#pragma unroll
            for (int o = 1; o < 4; o <<= 1) {
                s8 += __shfl_xor_sync(0xffffffffu, s8, o);
                m8 = fmaxf(m8, __shfl_xor_sync(0xffffffffu, m8, o));
            }
            if ((lane & 3) == 0)
                g_part[((size_t)inst * 1024 + row0 + row) * 32 + blockIdx.x * 2 + wn] =
                    make_float2(s8, m8);
        }
    }
}

// Coalesced reduce: 8 threads/row, float4 loads, shfl combine.
__global__ void __launch_bounds__(256) reduce_stats()
{
    int g = blockIdx.x * 256 + threadIdx.x;
    int row = g >> 3, sub = g & 7;
    const float4* p = (const float4*)(g_part + (size_t)row * 32) + sub * 2;
    float4 v0 = p[0], v1 = p[1];
    float s = (v0.x + v0.z) + (v1.x + v1.z);
    float m = fmaxf(fmaxf(v0.y, v0.w), fmaxf(v1.y, v1.w));
#pragma unroll
    for (int o = 1; o < 8; o <<= 1) {
        s += __shfl_xor_sync(0xffffffffu, s, o);
        m = fmaxf(m, __shfl_xor_sync(0xffffffffu, m, o));
    }
    if (sub == 0)
        g_stats2[row] = make_float2(s * (1.0f / 1024.0f), m);
}

// ---------------------------------------------------------------------------
// pv_mm: O = softmax_masked(S) @ V. A hi-only x B hi/lo (2 MMAs).
// Stage = A-hi(2048) | B-hi(1024) | B-lo(1024) floats = 16KB; 2 stages 32KB.
// Inline Z accumulation; 1/Z in epilogue.
// ---------------------------------------------------------------------------
__global__ void __launch_bounds__(256, 2) pv_mm()
{
    extern __shared__ float sm[];
    __shared__ float z_sm[128];
    const int tid = threadIdx.x;
    const int lane = tid & 31, wid = tid >> 5;
    const int wm = wid & 3, wn = wid >> 2;
    const int inst = blockIdx.z, row0 = blockIdx.y * 128;
    const float* A = g_S + ((size_t)inst << 20) + (size_t)row0 * 1024;
    const float* B = g_Vp + (size_t)inst * 65536;
    float* C = g_AO + (size_t)inst * 65536 + (size_t)row0 * 64;
    const float2* st = g_stats2 + inst * 1024 + row0;

    int tA[2], rA[2], cA[2], m0s[2];
    float2 st0[2], st1[2];
#pragma unroll
    for (int sl = 0; sl < 2; sl++) {
        int slot = tid + sl * 256;
        tA[sl] = slot >> 5; rA[sl] = (slot & 31) >> 2; cA[sl] = slot & 3;
        m0s[sl] = (tA[sl] & 7) * 16 + rA[sl];
        st0[sl] = st[m0s[sl]];
        st1[sl] = st[m0s[sl] + 8];
    }

    if (tid < 128) z_sm[tid] = 0.f;

    float acc[2][4][4];
#pragma unroll
    for (int mt = 0; mt < 2; mt++)
#pragma unroll
        for (int nt = 0; nt < 4; nt++)
#pragma unroll
            for (int e = 0; e < 4; e++) acc[mt][nt][e] = 0.f;

    float z0[2] = {0.f, 0.f}, z1[2] = {0.f, 0.f};
    float ax[2][4], bx[2][2];

    auto LDF = [&](int kb) {
#pragma unroll
        for (int sl = 0; sl < 2; sl++) {
            int tk = tA[sl] >> 3;
            const float* p = A + (size_t)m0s[sl] * 1024 + kb + tk * 8 + cA[sl];
            const float* q = p + 8 * 1024;
            ax[sl][0] = p[0]; ax[sl][1] = q[0];
            ax[sl][2] = p[4]; ax[sl][3] = q[4];
        }
#pragma unroll
        for (int sl = 0; sl < 2; sl++) {
            int tn = tA[sl] & 7, tk = tA[sl] >> 3;
            int n = tn * 8 + rA[sl];
            int kc = kb + tk * 8 + cA[sl];
            const float* p = B + (size_t)kc * 64 + n;
            bx[sl][0] = p[0]; bx[sl][1] = p[4 * 64];
        }
    };

    auto STF = [&](int s) {
        float* base = sm + s * 4096;
#pragma unroll
        for (int sl = 0; sl < 2; sl++) {
            float p0 = (ax[sl][0] > st0[sl].x) ? __expf(ax[sl][0] - st0[sl].y) : 0.f;
            float p1 = (ax[sl][1] > st1[sl].x) ? __expf(ax[sl][1] - st1[sl].y) : 0.f;
            float p2 = (ax[sl][2] > st0[sl].x) ? __expf(ax[sl][2] - st0[sl].y) : 0.f;
            float p3 = (ax[sl][3] > st1[sl].x) ? __expf(ax[sl][3] - st1[sl].y) : 0.f;
            z0[sl] += p0 + p2;
            z1[sl] += p1 + p3;
            float4 h;
            h.x = tf32r(p0); h.y = tf32r(p1); h.z = tf32r(p2); h.w = tf32r(p3);
            int slot = tid + sl * 256;
            int off = (slot >> 5) * 128 + (slot & 31) * 4;
            *(float4*)(base + off) = h;
        }
#pragma unroll
        for (int sl = 0; sl < 2; sl++) {
            float2 h, l;
            h.x = tf32r(bx[sl][0]); l.x = tf32r(bx[sl][0] - h.x);
            h.y = tf32r(bx[sl][1]); l.y = tf32r(bx[sl][1] - h.y);
            int slot = tid + sl * 256;
            int off = (slot >> 5) * 64 + (slot & 31) * 2;
            *(float2*)(base + 2048 + off) = h;
            *(float2*)(base + 3072 + off) = l;
        }
    };

    auto CMP = [&](int s) {
        const float* base = sm + s * 4096;
#pragma unroll
        for (int tk = 0; tk < 2; tk++) {
            uint4 ah[2];
            uint2 bh[4], bl[4];
#pragma unroll
            for (int mt = 0; mt < 2; mt++) {
                int tg = tk * 8 + wm * 2 + mt;
                ah[mt] = *(const uint4*)(base + tg * 128 + lane * 4);
            }
#pragma unroll
            for (int nt = 0; nt < 4; nt++) {
                int tg = tk * 8 + wn * 4 + nt;
                bh[nt] = *(const uint2*)(base + 2048 + tg * 64 + lane * 2);
                bl[nt] = *(const uint2*)(base + 3072 + tg * 64 + lane * 2);
            }
#pragma unroll
            for (int mt = 0; mt < 2; mt++)
#pragma unroll
                for (int nt = 0; nt < 4; nt++) {
                    MMA8(acc[mt][nt], (&ah[mt].x), (&bh[nt].x));
                    MMA8(acc[mt][nt], (&ah[mt].x), (&bl[nt].x));
                }
        }
    };

    LDF(0);
    STF(0);
    __syncthreads();
    for (int i = 0; i < 64; i++) {
        if (i + 1 < 64) LDF((i + 1) * 16);
        CMP(i & 1);
        if (i + 1 < 64) STF((i + 1) & 1);
        __syncthreads();
    }

#pragma unroll
    for (int sl = 0; sl < 2; sl++) {
        atomicAdd(&z_sm[m0s[sl]], z0[sl]);
        atomicAdd(&z_sm[m0s[sl] + 8], z1[sl]);
    }
    __syncthreads();

#pragma unroll
    for (int mt = 0; mt < 2; mt++)
#pragma unroll
        for (int nt = 0; nt < 4; nt++) {
            int row = wm * 32 + mt * 16 + (lane >> 2);
            int col = wn * 32 + nt * 8 + (lane & 3) * 2;
            float iz0 = 1.0f / z_sm[row];
            float iz1 = 1.0f / z_sm[row + 8];
            *(float2*)(C + (size_t)row * 64 + col) =
                make_float2(acc[mt][nt][0] * iz0, acc[mt][nt][1] * iz0);
            *(float2*)(C + (size_t)(row + 8) * 64 + col) =
                make_float2(acc[mt][nt][2] * iz1, acc[mt][nt][3] * iz1);
        }
}

// ---------------------------------------------------------------------------
extern "C" void kernel_launch(void* const* d_in, const int* in_sizes, int n_in,
                              void* d_out, int out_size)
{
    const float* x  = (const float*)d_in[0];
    const float* y  = (const float*)d_in[1];
    const float* qw = (const float*)d_in[2];
    const float* qb = (const float*)d_in[3];
    const float* kw = (const float*)d_in[4];
    const float* kb = (const float*)d_in[5];
    const float* vw = (const float*)d_in[6];
    const float* vb = (const float*)d_in[7];
    const float* ow = (const float*)d_in[8];
    const float* ob = (const float*)d_in[9];
    float* out = (float*)d_out;

    const int SMB = 49152;     // mm_core/qk: 2 stages * 24KB
    const int SMPV = 32768;    // pv: 2 stages * 16KB
    cudaFuncSetAttribute(proj_all, cudaFuncAttributeMaxDynamicSharedMemorySize, SMB);
    cudaFuncSetAttribute(qk_tf32,  cudaFuncAttributeMaxDynamicSharedMemorySize, SMB);
    cudaFuncSetAttribute(pv_mm,    cudaFuncAttributeMaxDynamicSharedMemorySize, SMPV);
    cudaFuncSetAttribute(out_mm,   cudaFuncAttributeMaxDynamicSharedMemorySize, SMB);

    proj_all<<<dim3(8, 64, 3), 256, SMB>>>(x, y, qw, qb, kw, kb, vw, vb);
    qk_tf32<<<dim3(16, 8, 64), 256, SMB>>>();
    reduce_stats<<<2048, 256>>>();
    pv_mm<<<dim3(1, 8, 64), 256, SMPV>>>();
    out_mm<<<dim3(8, 64, 1), 256, SMB>>>(ow, ob, out);
}

// round 10
// speedup vs baseline: 1.0194x; 1.0194x over previous
#include <cuda_runtime.h>
#include <cstdint>

// ---------------------------------------------------------------------------
// 64 attention instances: instance i uses contiguous slab [i*65536,(i+1)*65536)
// of each projection viewed as (1024,64).
// Accuracy (settled empirically over R3-R9): everything upstream of the
// mean-threshold mask must be EXACT fp32 (proj Q/K via FFMA chains) or
// 4-term tf32 on exact inputs (QK^T). Downstream smooth-error paths use
// 3-term (V-proj, out) / 2-term (PV) tf32 splits.
// This round: pv 2-stage -> 3-stage pipeline (numerics identical to R8).
// ---------------------------------------------------------------------------
#define NORMF 0.04419417382415922f   // 1/sqrt(512)

static __device__ float g_Qp[8192 * 512];
static __device__ float g_Kp[8192 * 512];
static __device__ float g_Vp[8192 * 512];
static __device__ float g_AO[8192 * 512];
static __device__ float g_S[67108864];        // 64*1024*1024 scores
static __device__ float2 g_part[65536 * 32];  // per (row, 32-col block): sum, max
static __device__ float2 g_stats2[65536];     // per row: mean, max

#define FMA2(d, a, b, c) \
    asm("fma.rn.f32x2 %0, %1, %2, %3;" : "=l"(d) : "l"(a), "l"(b), "l"(c))
#define PACK2(d, x) \
    asm("mov.b64 %0, {%1, %1};" : "=l"(d) : "r"(x))
#define UNPK2(lo, hi, d) \
    asm("mov.b64 {%0, %1}, %2;" : "=r"(lo), "=r"(hi) : "l"(d))

__device__ __forceinline__ float tf32r(float x) {
    uint32_t u;
    asm("cvt.rna.tf32.f32 %0, %1;" : "=r"(u) : "f"(x));
    return __uint_as_float(u);
}

#define MMA8(d, a, b)                                                          \
    asm volatile("mma.sync.aligned.m16n8k8.row.col.f32.tf32.tf32.f32 "         \
                 "{%0,%1,%2,%3}, {%4,%5,%6,%7}, {%8,%9}, {%0,%1,%2,%3};"       \
                 : "+f"((d)[0]), "+f"((d)[1]), "+f"((d)[2]), "+f"((d)[3])      \
                 : "r"((a)[0]), "r"((a)[1]), "r"((a)[2]), "r"((a)[3]),         \
                   "r"((b)[0]), "r"((b)[1]))

// ===========================================================================
// EXACT-FP32 PROJECTIONS (Q, K) — mask-critical, must bit-match reference.
// ===========================================================================
__global__ void __launch_bounds__(256, 2) proj_f32(
    const float* __restrict__ x, const float* __restrict__ y,
    const float* __restrict__ qw, const float* __restrict__ qb,
    const float* __restrict__ kw, const float* __restrict__ kb)
{
    const float* A    = blockIdx.z ? y  : x;
    const float* W    = blockIdx.z ? kw : qw;
    const float* bias = blockIdx.z ? kb : qb;
    float* C          = blockIdx.z ? g_Kp : g_Qp;

    __shared__ __align__(16) float As[2][16][132];
    __shared__ __align__(16) float Bs[2][16][128];

    const int tid = threadIdx.x;
    const int row0 = blockIdx.y * 128, col0 = blockIdx.x * 128;
    const int ty = tid >> 4, tx = tid & 15;
    const int ar = tid >> 1, ac = (tid & 1) * 8;
    const int br = tid >> 4, bc = (tid & 15) * 8;

    const float* Ap = A + (size_t)(row0 + ar) * 512 + ac;
    const float* Wp = W + (size_t)br * 512 + col0 + bc;

    uint64_t acc[8][4];
#pragma unroll
    for (int i = 0; i < 8; i++)
#pragma unroll
        for (int j = 0; j < 4; j++) acc[i][j] = 0ull;

    float4 a0, a1, b0, b1;
    auto LD = [&](int k0) {
        a0 = *(const float4*)(Ap + k0);
        a1 = *(const float4*)(Ap + k0 + 4);
        b0 = *(const float4*)(Wp + (size_t)k0 * 512);
        b1 = *(const float4*)(Wp + (size_t)k0 * 512 + 4);
    };
    auto ST = [&](int s) {
        As[s][ac + 0][ar] = a0.x; As[s][ac + 1][ar] = a0.y;
        As[s][ac + 2][ar] = a0.z; As[s][ac + 3][ar] = a0.w;
        As[s][ac + 4][ar] = a1.x; As[s][ac + 5][ar] = a1.y;
        As[s][ac + 6][ar] = a1.z; As[s][ac + 7][ar] = a1.w;
        *(float4*)&Bs[s][br][bc] = b0;
        *(float4*)&Bs[s][br][bc + 4] = b1;
    };
    auto CMP = [&](int s) {
#pragma unroll
        for (int kk = 0; kk < 16; kk++) {
            float4 av0 = *(const float4*)&As[s][kk][ty * 8];
            float4 av1 = *(const float4*)&As[s][kk][ty * 8 + 4];
            ulonglong2 bv0 = *(const ulonglong2*)&Bs[s][kk][tx * 4];
            ulonglong2 bv1 = *(const ulonglong2*)&Bs[s][kk][64 + tx * 4];
            uint64_t bp[4] = {bv0.x, bv0.y, bv1.x, bv1.y};
            float af[8] = {av0.x, av0.y, av0.z, av0.w, av1.x, av1.y, av1.z, av1.w};
#pragma unroll
            for (int i = 0; i < 8; i++) {
                uint64_t ap;
                PACK2(ap, __float_as_uint(af[i]));
#pragma unroll
                for (int j = 0; j < 4; j++) FMA2(acc[i][j], ap, bp[j], acc[i][j]);
            }
        }
    };

    LD(0);
    ST(0);
    __syncthreads();
    for (int i = 0; i < 32; i++) {
        if (i + 1 < 32) LD((i + 1) * 16);
        CMP(i & 1);
        if (i + 1 < 32) ST((i + 1) & 1);
        __syncthreads();
    }

#pragma unroll
    for (int i = 0; i < 8; i++) {
        int r = row0 + ty * 8 + i;
        int c0 = col0 + tx * 4, c1 = col0 + 64 + tx * 4;
        uint32_t e0, e1, e2, e3;
        float4 w0, w1;
        UNPK2(e0, e1, acc[i][0]); UNPK2(e2, e3, acc[i][1]);
        w0.x = __uint_as_float(e0) + bias[c0 + 0];
        w0.y = __uint_as_float(e1) + bias[c0 + 1];
        w0.z = __uint_as_float(e2) + bias[c0 + 2];
        w0.w = __uint_as_float(e3) + bias[c0 + 3];
        UNPK2(e0, e1, acc[i][2]); UNPK2(e2, e3, acc[i][3]);
        w1.x = __uint_as_float(e0) + bias[c1 + 0];
        w1.y = __uint_as_float(e1) + bias[c1 + 1];
        w1.z = __uint_as_float(e2) + bias[c1 + 2];
        w1.w = __uint_as_float(e3) + bias[c1 + 3];
        *(float4*)(C + (size_t)r * 512 + c0) = w0;
        *(float4*)(C + (size_t)r * 512 + c1) = w1;
    }
}

// ===========================================================================
// qk_tf32: S = (Q @ K^T) * NORM on exact Q/K. 4-term split (hh+hl+lh+ll).
// Fused per-(row, 32-col) stat partials. Block tile 128x64x16.
// ===========================================================================
__global__ void __launch_bounds__(256, 2) qk_tf32()
{
    extern __shared__ float sm[];
    const int tid = threadIdx.x;
    const int lane = tid & 31, wid = tid >> 5;
    const int wm = wid & 3, wn = wid >> 2;
    const int inst = blockIdx.z;
    const int row0 = blockIdx.y * 128, col0 = blockIdx.x * 64;
    const float* A = g_Qp + (size_t)inst * 65536 + (size_t)row0 * 64;
    const float* B = g_Kp + (size_t)inst * 65536 + (size_t)col0 * 64;
    float* Sout = g_S + ((size_t)inst << 20) + (size_t)row0 * 1024 + col0;

    int tA[2], rA[2], cA[2];
#pragma unroll
    for (int sl = 0; sl < 2; sl++) {
        int slot = tid + sl * 256;
        tA[sl] = slot >> 5; rA[sl] = (slot & 31) >> 2; cA[sl] = slot & 3;
    }

    float acc[2][4][4];
#pragma unroll
    for (int mt = 0; mt < 2; mt++)
#pragma unroll
        for (int nt = 0; nt < 4; nt++)
#pragma unroll
            for (int e = 0; e < 4; e++) acc[mt][nt][e] = 0.f;

    float ax[2][4], bx[2][2];

    auto LDF = [&](int kb) {
#pragma unroll
        for (int sl = 0; sl < 2; sl++) {
            int tm = tA[sl] & 7, tk = tA[sl] >> 3;
            const float* p = A + (size_t)(tm * 16 + rA[sl]) * 64 + kb + tk * 8 + cA[sl];
            const float* q = p + 8 * 64;
            ax[sl][0] = p[0]; ax[sl][1] = q[0];
            ax[sl][2] = p[4]; ax[sl][3] = q[4];
        }
#pragma unroll
        for (int sl = 0; sl < 2; sl++) {
            int tn = tA[sl] & 7, tk = tA[sl] >> 3;
            const float* p = B + (size_t)(tn * 8 + rA[sl]) * 64 + kb + tk * 8 + cA[sl];
            bx[sl][0] = p[0]; bx[sl][1] = p[4];
        }
    };

    auto STF = [&](int s) {
        float* base = sm + s * 6144;
#pragma unroll
        for (int sl = 0; sl < 2; sl++) {
            float4 h, l;
            h.x = tf32r(ax[sl][0]); l.x = tf32r(ax[sl][0] - h.x);
            h.y = tf32r(ax[sl][1]); l.y = tf32r(ax[sl][1] - h.y);
            h.z = tf32r(ax[sl][2]); l.z = tf32r(ax[sl][2] - h.z);
            h.w = tf32r(ax[sl][3]); l.w = tf32r(ax[sl][3] - h.w);
            int slot = tid + sl * 256;
            int off = (slot >> 5) * 128 + (slot & 31) * 4;
            *(float4*)(base + off) = h;
            *(float4*)(base + 2048 + off) = l;
        }
#pragma unroll
        for (int sl = 0; sl < 2; sl++) {
            float2 h, l;
            h.x = tf32r(bx[sl][0]); l.x = tf32r(bx[sl][0] - h.x);
            h.y = tf32r(bx[sl][1]); l.y = tf32r(bx[sl][1] - h.y);
            int slot = tid + sl * 256;
            int off = (slot >> 5) * 64 + (slot & 31) * 2;
            *(float2*)(base + 4096 + off) = h;
            *(float2*)(base + 5120 + off) = l;
        }
    };

    auto CMP = [&](int s) {
        const float* base = sm + s * 6144;
#pragma unroll
        for (int tk = 0; tk < 2; tk++) {
            uint4 ah[2], al[2];
            uint2 bh[4], bl[4];
#pragma unroll
            for (int mt = 0; mt < 2; mt++) {
                int tg = tk * 8 + wm * 2 + mt;
                ah[mt] = *(const uint4*)(base + tg * 128 + lane * 4);
                al[mt] = *(const uint4*)(base + 2048 + tg * 128 + lane * 4);
            }
#pragma unroll
            for (int nt = 0; nt < 4; nt++) {
                int tg = tk * 8 + wn * 4 + nt;
                bh[nt] = *(const uint2*)(base + 4096 + tg * 64 + lane * 2);
                bl[nt] = *(const uint2*)(base + 5120 + tg * 64 + lane * 2);
            }
#pragma unroll
            for (int mt = 0; mt < 2; mt++)
#pragma unroll
                for (int nt = 0; nt < 4; nt++) {
                    MMA8(acc[mt][nt], (&ah[mt].x), (&bh[nt].x));
                    MMA8(acc[mt][nt], (&ah[mt].x), (&bl[nt].x));
                    MMA8(acc[mt][nt], (&al[mt].x), (&bh[nt].x));
                    MMA8(acc[mt][nt], (&al[mt].x), (&bl[nt].x));
                }
        }
    };

    LDF(0);
    STF(0);
    __syncthreads();
    for (int i = 0; i < 4; i++) {
        if (i + 1 < 4) LDF((i + 1) * 16);
        CMP(i & 1);
        if (i + 1 < 4) STF((i + 1) & 1);
        __syncthreads();
    }

#pragma unroll
    for (int mt = 0; mt < 2; mt++) {
#pragma unroll
        for (int half = 0; half < 2; half++) {
            int row = wm * 32 + mt * 16 + (lane >> 2) + half * 8;
            float v[8];
#pragma unroll
            for (int nt = 0; nt < 4; nt++) {
                v[nt * 2 + 0] = acc[mt][nt][half * 2 + 0] * NORMF;
                v[nt * 2 + 1] = acc[mt][nt][half * 2 + 1] * NORMF;
                int col = wn * 32 + nt * 8 + (lane & 3) * 2;
                *(float2*)(Sout + (size_t)row * 1024 + col) =
                    make_float2(v[nt * 2], v[nt * 2 + 1]);
            }
            float s8 = ((v[0] + v[1]) + (v[2] + v[3])) + ((v[4] + v[5]) + (v[6] + v[7]));
            float m8 = fmaxf(fmaxf(fmaxf(v[0], v[1]), fmaxf(v[2], v[3])),
                             fmaxf(fmaxf(v[4], v[5]), fmaxf(v[6], v[7])));
#pragma unroll
            for (int o = 1; o < 4; o <<= 1) {
                s8 += __shfl_xor_sync(0xffffffffu, s8, o);
                m8 = fmaxf(m8, __shfl_xor_sync(0xffffffffu, m8, o));
            }
            if ((lane & 3) == 0)
                g_part[((size_t)inst * 1024 + row0 + row) * 32 + blockIdx.x * 2 + wn] =
                    make_float2(s8, m8);
        }
    }
}

// Coalesced reduce: 8 threads/row, float4 loads, shfl combine.
__global__ void __launch_bounds__(256) reduce_stats()
{
    int g = blockIdx.x * 256 + threadIdx.x;
    int row = g >> 3, sub = g & 7;
    const float4* p = (const float4*)(g_part + (size_t)row * 32) + sub * 2;
    float4 v0 = p[0], v1 = p[1];
    float s = (v0.x + v0.z) + (v1.x + v1.z);
    float m = fmaxf(fmaxf(v0.y, v0.w), fmaxf(v1.y, v1.w));
#pragma unroll
    for (int o = 1; o < 8; o <<= 1) {
        s += __shfl_xor_sync(0xffffffffu, s, o);
        m = fmaxf(m, __shfl_xor_sync(0xffffffffu, m, o));
    }
    if (sub == 0)
        g_stats2[row] = make_float2(s * (1.0f / 1024.0f), m);
}

// ===========================================================================
// mm_body: 3xTF32 split GEMM (V-proj, out). B is K x 64 (B[k][n]).
// ===========================================================================
__device__ __forceinline__ void mm_body(
    const float* __restrict__ A, int lda,
    const float* __restrict__ B, int ldb,
    const float* __restrict__ bias,
    float* __restrict__ C, int ldc, int ktot)
{
    extern __shared__ float sm[];
    const int tid = threadIdx.x;
    const int lane = tid & 31, wid = tid >> 5;
    const int wm = wid & 3, wn = wid >> 2;

    int tA[2], rA[2], cA[2];
#pragma unroll
    for (int sl = 0; sl < 2; sl++) {
        int slot = tid + sl * 256;
        tA[sl] = slot >> 5; rA[sl] = (slot & 31) >> 2; cA[sl] = slot & 3;
    }

    float acc[2][4][4];
#pragma unroll
    for (int mt = 0; mt < 2; mt++)
#pragma unroll
        for (int nt = 0; nt < 4; nt++)
#pragma unroll
            for (int e = 0; e < 4; e++) acc[mt][nt][e] = 0.f;

    float ax[2][4], bx[2][2];

    auto LDF = [&](int kb) {
#pragma unroll
        for (int sl = 0; sl < 2; sl++) {
            int tm = tA[sl] & 7, tk = tA[sl] >> 3;
            const float* p = A + (size_t)(tm * 16 + rA[sl]) * lda + kb + tk * 8 + cA[sl];
            const float* q = p + 8 * (size_t)lda;
            ax[sl][0] = p[0]; ax[sl][1] = q[0];
            ax[sl][2] = p[4]; ax[sl][3] = q[4];
        }
#pragma unroll
        for (int sl = 0; sl < 2; sl++) {
            int tn = tA[sl] & 7, tk = tA[sl] >> 3;
            int n = tn * 8 + rA[sl];
            int kc = kb + tk * 8 + cA[sl];
            const float* p = B + (size_t)kc * ldb + n;
            bx[sl][0] = p[0]; bx[sl][1] = p[4 * (size_t)ldb];
        }
    };

    auto STF = [&](int s) {
        float* base = sm + s * 6144;
#pragma unroll
        for (int sl = 0; sl < 2; sl++) {
            float4 h, l;
            h.x = tf32r(ax[sl][0]); l.x = tf32r(ax[sl][0] - h.x);
            h.y = tf32r(ax[sl][1]); l.y = tf32r(ax[sl][1] - h.y);
            h.z = tf32r(ax[sl][2]); l.z = tf32r(ax[sl][2] - h.z);
            h.w = tf32r(ax[sl][3]); l.w = tf32r(ax[sl][3] - h.w);
            int slot = tid + sl * 256;
            int off = (slot >> 5) * 128 + (slot & 31) * 4;
            *(float4*)(base + off) = h;
            *(float4*)(base + 2048 + off) = l;
        }
#pragma unroll
        for (int sl = 0; sl < 2; sl++) {
            float2 h, l;
            h.x = tf32r(bx[sl][0]); l.x = tf32r(bx[sl][0] - h.x);
            h.y = tf32r(bx[sl][1]); l.y = tf32r(bx[sl][1] - h.y);
            int slot = tid + sl * 256;
            int off = (slot >> 5) * 64 + (slot & 31) * 2;
            *(float2*)(base + 4096 + off) = h;
            *(float2*)(base + 5120 + off) = l;
        }
    };

    auto CMP = [&](int s) {
        const float* base = sm + s * 6144;
#pragma unroll
        for (int tk = 0; tk < 2; tk++) {
            uint4 ah[2], al[2];
            uint2 bh[4], bl[4];
#pragma unroll
            for (int mt = 0; mt < 2; mt++) {
                int tg = tk * 8 + wm * 2 + mt;
                ah[mt] = *(const uint4*)(base + tg * 128 + lane * 4);
                al[mt] = *(const uint4*)(base + 2048 + tg * 128 + lane * 4);
            }
#pragma unroll
            for (int nt = 0; nt < 4; nt++) {
                int tg = tk * 8 + wn * 4 + nt;
                bh[nt] = *(const uint2*)(base + 4096 + tg * 64 + lane * 2);
                bl[nt] = *(const uint2*)(base + 5120 + tg * 64 + lane * 2);
            }
#pragma unroll
            for (int mt = 0; mt < 2; mt++)
#pragma unroll
                for (int nt = 0; nt < 4; nt++) {
                    MMA8(acc[mt][nt], (&ah[mt].x), (&bh[nt].x));
                    MMA8(acc[mt][nt], (&ah[mt].x), (&bl[nt].x));
                    MMA8(acc[mt][nt], (&al[mt].x), (&bh[nt].x));
                }
        }
    };

    const int nk = ktot / 16;
    LDF(0);
    STF(0);
    __syncthreads();
    for (int i = 0; i < nk; i++) {
        if (i + 1 < nk) LDF((i + 1) * 16);
        CMP(i & 1);
        if (i + 1 < nk) STF((i + 1) & 1);
        __syncthreads();
    }

#pragma unroll
    for (int mt = 0; mt < 2; mt++)
#pragma unroll
        for (int nt = 0; nt < 4; nt++) {
            int row = wm * 32 + mt * 16 + (lane >> 2);
            int col = wn * 32 + nt * 8 + (lane & 3) * 2;
            float b0 = bias[col], b1 = bias[col + 1];
            *(float2*)(C + (size_t)row * ldc + col) =
                make_float2(acc[mt][nt][0] + b0, acc[mt][nt][1] + b1);
            *(float2*)(C + (size_t)(row + 8) * ldc + col) =
                make_float2(acc[mt][nt][2] + b0, acc[mt][nt][3] + b1);
        }
}

__global__ void __launch_bounds__(256, 2) projv_mm(
    const float* __restrict__ y,
    const float* __restrict__ vw, const float* __restrict__ vb)
{
    int row0 = blockIdx.y * 128, col0 = blockIdx.x * 64;
    mm_body(y + (size_t)row0 * 512, 512, vw + col0, 512,
            vb + col0, g_Vp + (size_t)row0 * 512 + col0, 512, 512);
}

__global__ void __launch_bounds__(256, 2) out_mm(
    const float* __restrict__ ow, const float* __restrict__ ob,
    float* __restrict__ out)
{
    int row0 = blockIdx.y * 128, col0 = blockIdx.x * 64;
    mm_body(g_AO + (size_t)row0 * 512, 512, ow + col0, 512,
            ob + col0, out + (size_t)row0 * 512 + col0, 512, 512);
}

// ---------------------------------------------------------------------------
// pv_mm: O = softmax_masked(S) @ V. A hi-only x B hi/lo (2 MMAs per (mt,nt)).
// THREE-stage pipeline: stage written at iter i is consumed at iter i+2,
// removing the STS->bar->LDS immediate dependency. Numerics identical to R8.
// Stage = A-hi(2048) | B-hi(1024) | B-lo(1024) floats = 16KB; 3 stages 48KB.
// ---------------------------------------------------------------------------
__global__ void __launch_bounds__(256, 2) pv_mm()
{
    extern __shared__ float sm[];
    __shared__ float z_sm[128];
    const int tid = threadIdx.x;
    const int lane = tid & 31, wid = tid >> 5;
    const int wm = wid & 3, wn = wid >> 2;
    const int inst = blockIdx.z, row0 = blockIdx.y * 128;
    const float* A = g_S + ((size_t)inst << 20) + (size_t)row0 * 1024;
    const float* B = g_Vp + (size_t)inst * 65536;
    float* C = g_AO + (size_t)inst * 65536 + (size_t)row0 * 64;
    const float2* st = g_stats2 + inst * 1024 + row0;

    int tA[2], rA[2], cA[2], m0s[2];
    float2 st0[2], st1[2];
#pragma unroll
    for (int sl = 0; sl < 2; sl++) {
        int slot = tid + sl * 256;
        tA[sl] = slot >> 5; rA[sl] = (slot & 31) >> 2; cA[sl] = slot & 3;
        m0s[sl] = (tA[sl] & 7) * 16 + rA[sl];
        st0[sl] = st[m0s[sl]];
        st1[sl] = st[m0s[sl] + 8];
    }

    if (tid < 128) z_sm[tid] = 0.f;

    float acc[2][4][4];
#pragma unroll
    for (int mt = 0; mt < 2; mt++)
#pragma unroll
        for (int nt = 0; nt < 4; nt++)
#pragma unroll
            for (int e = 0; e < 4; e++) acc[mt][nt][e] = 0.f;

    float z0[2] = {0.f, 0.f}, z1[2] = {0.f, 0.f};
    float ax[2][4], bx[2][2];

    auto LDF = [&](int kb) {
#pragma unroll
        for (int sl = 0; sl < 2; sl++) {
            int tk = tA[sl] >> 3;
            const float* p = A + (size_t)m0s[sl] * 1024 + kb + tk * 8 + cA[sl];
            const float* q = p + 8 * 1024;
            ax[sl][0] = p[0]; ax[sl][1] = q[0];
            ax[sl][2] = p[4]; ax[sl][3] = q[4];
        }
#pragma unroll
        for (int sl = 0; sl < 2; sl++) {
            int tn = tA[sl] & 7, tk = tA[sl] >> 3;
            int n = tn * 8 + rA[sl];
            int kc = kb + tk * 8 + cA[sl];
            const float* p = B + (size_t)kc * 64 + n;
            bx[sl][0] = p[0]; bx[sl][1] = p[4 * 64];
        }
    };

    auto STF = [&](int s) {
        float* base = sm + s * 4096;
#pragma unroll
        for (int sl = 0; sl < 2; sl++) {
            float p0 = (ax[sl][0] > st0[sl].x) ? __expf(ax[sl][0] - st0[sl].y) : 0.f;
            float p1 = (ax[sl][1] > st1[sl].x) ? __expf(ax[sl][1] - st1[sl].y) : 0.f;
            float p2 = (ax[sl][2] > st0[sl].x) ? __expf(ax[sl][2] - st0[sl].y) : 0.f;
            float p3 = (ax[sl][3] > st1[sl].x) ? __expf(ax[sl][3] - st1[sl].y) : 0.f;
            z0[sl] += p0 + p2;
            z1[sl] += p1 + p3;
            float4 h;
            h.x = tf32r(p0); h.y = tf32r(p1); h.z = tf32r(p2); h.w = tf32r(p3);
            int slot = tid + sl * 256;
            int off = (slot >> 5) * 128 + (slot & 31) * 4;
            *(float4*)(base + off) = h;
        }
#pragma unroll
        for (int sl = 0; sl < 2; sl++) {
            float2 h, l;
            h.x = tf32r(bx[sl][0]); l.x = tf32r(bx[sl][0] - h.x);
            h.y = tf32r(bx[sl][1]); l.y = tf32r(bx[sl][1] - h.y);
            int slot = tid + sl * 256;
            int off = (slot >> 5) * 64 + (slot & 31) * 2;
            *(float2*)(base + 2048 + off) = h;
            *(float2*)(base + 3072 + off) = l;
        }
    };

    auto CMP = [&](int s) {
        const float* base = sm + s * 4096;
#pragma unroll
        for (int tk = 0; tk < 2; tk++) {
            uint4 ah[2];
            uint2 bh[4], bl[4];
#pragma unroll
            for (int mt = 0; mt < 2; mt++) {
                int tg = tk * 8 + wm * 2 + mt;
                ah[mt] = *(const uint4*)(base + tg * 128 + lane * 4);
            }
#pragma unroll
            for (int nt = 0; nt < 4; nt++) {
                int tg = tk * 8 + wn * 4 + nt;
                bh[nt] = *(const uint2*)(base + 2048 + tg * 64 + lane * 2);
                bl[nt] = *(const uint2*)(base + 3072 + tg * 64 + lane * 2);
            }
#pragma unroll
            for (int mt = 0; mt < 2; mt++)
#pragma unroll
                for (int nt = 0; nt < 4; nt++) {
                    MMA8(acc[mt][nt], (&ah[mt].x), (&bh[nt].x));
                    MMA8(acc[mt][nt], (&ah[mt].x), (&bl[nt].x));
                }
        }
    };

    // 3-stage software pipeline
    LDF(0);
    STF(0);
    LDF(16);
    STF(1);
    __syncthreads();
    int s_cmp = 0, s_fill = 2;
    for (int i = 0; i < 64; i++) {
        if (i + 2 < 64) LDF((i + 2) * 16);
        CMP(s_cmp);
        if (i + 2 < 64) STF(s_fill);
        __syncthreads();
        s_cmp = (s_cmp == 2) ? 0 : s_cmp + 1;
        s_fill = (s_fill == 2) ? 0 : s_fill + 1;
    }

#pragma unroll
    for (int sl = 0; sl < 2; sl++) {
        atomicAdd(&z_sm[m0s[sl]], z0[sl]);
        atomicAdd(&z_sm[m0s[sl] + 8], z1[sl]);
    }
    __syncthreads();

#pragma unroll
    for (int mt = 0; mt < 2; mt++)
#pragma unroll
        for (int nt = 0; nt < 4; nt++) {
            int row = wm * 32 + mt * 16 + (lane >> 2);
            int col = wn * 32 + nt * 8 + (lane & 3) * 2;
            float iz0 = 1.0f / z_sm[row];
            float iz1 = 1.0f / z_sm[row + 8];
            *(float2*)(C + (size_t)row * 64 + col) =
                make_float2(acc[mt][nt][0] * iz0, acc[mt][nt][1] * iz0);
            *(float2*)(C + (size_t)(row + 8) * 64 + col) =
                make_float2(acc[mt][nt][2] * iz1, acc[mt][nt][3] * iz1);
        }
}

// ---------------------------------------------------------------------------
extern "C" void kernel_launch(void* const* d_in, const int* in_sizes, int n_in,
                              void* d_out, int out_size)
{
    const float* x  = (const float*)d_in[0];
    const float* y  = (const float*)d_in[1];
    const float* qw = (const float*)d_in[2];
    const float* qb = (const float*)d_in[3];
    const float* kw = (const float*)d_in[4];
    const float* kb = (const float*)d_in[5];
    const float* vw = (const float*)d_in[6];
    const float* vb = (const float*)d_in[7];
    const float* ow = (const float*)d_in[8];
    const float* ob = (const float*)d_in[9];
    float* out = (float*)d_out;

    const int SMB = 49152;     // mm_body/qk: 2 stages * 24KB
    const int SMPV = 49152;    // pv: 3 stages * 16KB
    cudaFuncSetAttribute(qk_tf32,  cudaFuncAttributeMaxDynamicSharedMemorySize, SMB);
    cudaFuncSetAttribute(projv_mm, cudaFuncAttributeMaxDynamicSharedMemorySize, SMB);
    cudaFuncSetAttribute(pv_mm,    cudaFuncAttributeMaxDynamicSharedMemorySize, SMPV);
    cudaFuncSetAttribute(out_mm,   cudaFuncAttributeMaxDynamicSharedMemorySize, SMB);

    proj_f32<<<dim3(4, 64, 2), 256>>>(x, y, qw, qb, kw, kb);
    projv_mm<<<dim3(8, 64, 1), 256, SMB>>>(y, vw, vb);
    qk_tf32<<<dim3(16, 8, 64), 256, SMB>>>();
    reduce_stats<<<2048, 256>>>();
    pv_mm<<<dim3(1, 8, 64), 256, SMPV>>>();
    out_mm<<<dim3(8, 64, 1), 256, SMB>>>(ow, ob, out);
}